// round 12
// baseline (speedup 1.0000x reference)
#include <cuda_runtime.h>
#include <cuda_bf16.h>
#include <cstdint>
#include <math.h>

#define BATCH 8
#define CIN   512
#define HW    1024
#define DQKV  768
#define DVDIM 256
#define COUT  512

// ---------------- scratch (static device globals; allocation-free rule) ----
__device__ float g_attn[(size_t)BATCH * DVDIM * HW]; // 8 MB [b][c][s] (ref-reshape layout)

__device__ __nv_bfloat16 g_qt_hi[(size_t)BATCH * HW * DQKV];  // 12 MB [b][s][o] qkvT hi
__device__ __nv_bfloat16 g_qt_lo[(size_t)BATCH * HW * DQKV];  // 12 MB [b][s][o] qkvT lo
__device__ __nv_bfloat16 g_wqkv_hi[DQKV * CIN],  g_wqkv_lo[DQKV * CIN];
__device__ __nv_bfloat16 g_wattn_hi[COUT * DVDIM], g_wattn_lo[COUT * DVDIM];
__device__ __nv_bfloat16 g_xt_hi[(size_t)BATCH * HW * CIN],  g_xt_lo[(size_t)BATCH * HW * CIN];    // [b][s][c]
__device__ __nv_bfloat16 g_at_hi[(size_t)BATCH * HW * DVDIM], g_at_lo[(size_t)BATCH * HW * DVDIM]; // [b][s][c]

// ---------------- helpers ---------------------------------------------------
__device__ __forceinline__ uint32_t smem_u32(const void* p) {
    uint32_t a;
    asm("{ .reg .u64 t; cvta.to.shared.u64 t, %1; cvt.u32.u64 %0, t; }" : "=r"(a) : "l"(p));
    return a;
}

#define LDSM_X4(r0, r1, r2, r3, addr)                                           \
    asm volatile("ldmatrix.sync.aligned.m8n8.x4.shared.b16 {%0,%1,%2,%3}, [%4];"\
                 : "=r"(r0), "=r"(r1), "=r"(r2), "=r"(r3) : "r"(addr))
#define LDSM_X2(r0, r1, addr)                                                   \
    asm volatile("ldmatrix.sync.aligned.m8n8.x2.shared.b16 {%0,%1}, [%2];"      \
                 : "=r"(r0), "=r"(r1) : "r"(addr))
#define LDSM_X2T(r0, r1, addr)                                                  \
    asm volatile("ldmatrix.sync.aligned.m8n8.x2.trans.shared.b16 {%0,%1}, [%2];"\
                 : "=r"(r0), "=r"(r1) : "r"(addr))

#define CP_ASYNC16(dst, src)                                                    \
    asm volatile("cp.async.cg.shared.global [%0], [%1], 16;"                    \
                 :: "r"(dst), "l"(src))
#define CP_COMMIT() asm volatile("cp.async.commit_group;" ::: "memory")
#define CP_WAIT1()  asm volatile("cp.async.wait_group 1;" ::: "memory")
#define CP_WAIT0()  asm volatile("cp.async.wait_group 0;" ::: "memory")

__device__ __forceinline__ void mma_bf16(float* c, const uint32_t* a, const uint32_t* b) {
    asm volatile("mma.sync.aligned.m16n8k16.row.col.f32.bf16.bf16.f32 "
                 "{%0,%1,%2,%3}, {%4,%5,%6,%7}, {%8,%9}, {%0,%1,%2,%3};"
                 : "+f"(c[0]), "+f"(c[1]), "+f"(c[2]), "+f"(c[3])
                 : "r"(a[0]), "r"(a[1]), "r"(a[2]), "r"(a[3]), "r"(b[0]), "r"(b[1]));
}

// FMA-pipe exp (no MUFU), |rel err| ~ 3e-7. Logits are tiny (sigma~0.2).
__device__ __forceinline__ float fast_exp(float x) {
    const float t  = x * 1.442695041f;
    const float tm = t + 12582912.0f;
    const int   k  = __float_as_int(tm) - 0x4b400000;
    const float f  = t - (tm - 12582912.0f);
    float p = 1.33336498e-3f;
    p = fmaf(p, f, 9.81094252e-3f);
    p = fmaf(p, f, 5.55036691e-2f);
    p = fmaf(p, f, 2.40226597e-1f);
    p = fmaf(p, f, 6.93147182e-1f);
    p = fmaf(p, f, 1.0f);
    return __int_as_float(__float_as_int(p) + (k << 23));
}

// ---------------- conversion kernels ---------------------------------------
__global__ void split_kernel(const float* __restrict__ w,
                             __nv_bfloat16* __restrict__ hi,
                             __nv_bfloat16* __restrict__ lo, int n) {
    int i = blockIdx.x * 256 + threadIdx.x;
    if (i < n) {
        float v = w[i];
        __nv_bfloat16 h = __float2bfloat16(v);
        hi[i] = h;
        lo[i] = __float2bfloat16(v - __bfloat162float(h));
    }
}

// X[b][C][S] -> out[b][S][C] bf16 hi/lo (transpose + split)
__global__ void tsplit_kernel(const float* __restrict__ X,
                              __nv_bfloat16* __restrict__ hi,
                              __nv_bfloat16* __restrict__ lo, int C, int S) {
    __shared__ float t[32][33];
    const int b = blockIdx.z;
    const int c0 = blockIdx.y * 32, s0 = blockIdx.x * 32;
    const int tx = threadIdx.x, ty = threadIdx.y; // 32 x 8
    const float* Xb = X + (size_t)b * C * S;
    #pragma unroll
    for (int i = 0; i < 32; i += 8)
        t[ty + i][tx] = Xb[(size_t)(c0 + ty + i) * S + s0 + tx];
    __syncthreads();
    const size_t ob = (size_t)b * S * C;
    #pragma unroll
    for (int i = 0; i < 32; i += 8) {
        float v = t[tx][ty + i];
        __nv_bfloat16 h = __float2bfloat16(v);
        size_t idx = ob + (size_t)(s0 + ty + i) * C + c0 + tx;
        hi[idx] = h;
        lo[idx] = __float2bfloat16(v - __bfloat162float(h));
    }
}

// ---------------- HMMA split-bf16 GEMM, cp.async 2-stage pipeline -----------
#define BK2    32
#define RPAD2  40
#define TILE2  (128 * RPAD2 * 2)   // 10240 B
#define STAGE2 (4 * TILE2)         // 40960 B
#define GM_SMEM (2 * STAGE2)       // 81920 B

template<int K, bool COLB, bool SPLITOUT>
__global__ __launch_bounds__(256) void gemm_mma(
    const __nv_bfloat16* __restrict__ Ahi_g, const __nv_bfloat16* __restrict__ Alo_g,
    const __nv_bfloat16* __restrict__ Bhi_g, const __nv_bfloat16* __restrict__ Blo_g,
    const float* __restrict__ bias, float* __restrict__ C_all,
    __nv_bfloat16* __restrict__ Chi_all, __nv_bfloat16* __restrict__ Clo_all,
    int M, int N, size_t aStride, size_t bStride, int scale_limit, float scale)
{
    extern __shared__ char smem[];
    const uint32_t sb = smem_u32(smem);

    const int tid  = threadIdx.x;
    const int wid  = tid >> 5;
    const int lane = tid & 31;
    const int wm = wid >> 2;
    const int wn = wid & 3;
    const int b  = blockIdx.z, m0 = blockIdx.y * 128, n0 = blockIdx.x * 128;

    const __nv_bfloat16* gsrc[4];
    gsrc[0] = Ahi_g + (size_t)b * aStride + (size_t)m0 * K;
    gsrc[1] = Alo_g + (size_t)b * aStride + (size_t)m0 * K;
    gsrc[2] = Bhi_g + (size_t)b * bStride + (size_t)n0 * K;
    gsrc[3] = Blo_g + (size_t)b * bStride + (size_t)n0 * K;

    const int a_row  = wm * 64 + (lane & 7) + ((lane >> 3) & 1) * 8;
    const int a_koff = ((lane >> 3) >> 1) * 8;
    const int b_row  = wn * 32 + (lane & 7);
    const int b_koff = ((lane >> 3) & 1) * 8;

    float acc[4][4][4] = {};
    constexpr int NCH = K / BK2;

    #pragma unroll
    for (int it = 0; it < 8; it++) {
        const int slot = it * 256 + tid;
        const int t  = slot >> 9;
        const int in_ = slot & 511;
        const int r  = in_ >> 2;
        const int cg = in_ & 3;
        CP_ASYNC16(sb + t * TILE2 + r * (RPAD2 * 2) + cg * 16,
                   gsrc[t] + (size_t)r * K + cg * 8);
    }
    CP_COMMIT();

    for (int ch = 0; ch < NCH; ch++) {
        if (ch + 1 < NCH) {
            const uint32_t dstb = sb + ((ch + 1) & 1) * STAGE2;
            const int c0k = (ch + 1) * BK2;
            #pragma unroll
            for (int it = 0; it < 8; it++) {
                const int slot = it * 256 + tid;
                const int t  = slot >> 9;
                const int in_ = slot & 511;
                const int r  = in_ >> 2;
                const int cg = in_ & 3;
                CP_ASYNC16(dstb + t * TILE2 + r * (RPAD2 * 2) + cg * 16,
                           gsrc[t] + (size_t)r * K + c0k + cg * 8);
            }
            CP_COMMIT();
            CP_WAIT1();
        } else {
            CP_WAIT0();
        }
        __syncthreads();

        const uint32_t st = sb + (ch & 1) * STAGE2;
        const uint32_t sAhi_u = st, sAlo_u = st + TILE2;
        const uint32_t sBhi_u = st + 2 * TILE2, sBlo_u = st + 3 * TILE2;

        #pragma unroll
        for (int ks = 0; ks < BK2 / 16; ks++) {
            const int kb = ks * 16;
            uint32_t bh[4][2], bl[4][2];
            #pragma unroll
            for (int nt = 0; nt < 4; nt++) {
                const uint32_t off = (uint32_t)((b_row + nt * 8) * (RPAD2 * 2) +
                                                (kb + b_koff) * 2);
                LDSM_X2(bh[nt][0], bh[nt][1], sBhi_u + off);
                LDSM_X2(bl[nt][0], bl[nt][1], sBlo_u + off);
            }
            #pragma unroll
            for (int mt = 0; mt < 4; mt++) {
                const uint32_t off = (uint32_t)((a_row + mt * 16) * (RPAD2 * 2) +
                                                (kb + a_koff) * 2);
                uint32_t ah[4], al[4];
                LDSM_X4(ah[0], ah[1], ah[2], ah[3], sAhi_u + off);
                LDSM_X4(al[0], al[1], al[2], al[3], sAlo_u + off);
                #pragma unroll
                for (int nt = 0; nt < 4; nt++) {
                    mma_bf16(acc[mt][nt], ah, bh[nt]);
                    mma_bf16(acc[mt][nt], ah, bl[nt]);
                    mma_bf16(acc[mt][nt], al, bh[nt]);
                }
            }
        }
        __syncthreads();
    }

    const int col0 = n0 + wn * 32 + (lane & 3) * 2;
    #pragma unroll
    for (int mt = 0; mt < 4; mt++) {
        const int r0 = m0 + wm * 64 + mt * 16 + (lane >> 2);
        const int r1 = r0 + 8;
        if (COLB) {
            #pragma unroll
            for (int nt = 0; nt < 4; nt++) {
                const int cx = col0 + nt * 8, cy = cx + 1;
                const float bvx = bias[cx], bvy = bias[cy];
                const float scx = (cx < scale_limit) ? scale : 1.0f;
                const float scy = (cy < scale_limit) ? scale : 1.0f;
                const float v0x = (acc[mt][nt][0] + bvx) * scx;
                const float v0y = (acc[mt][nt][1] + bvy) * scy;
                const float v1x = (acc[mt][nt][2] + bvx) * scx;
                const float v1y = (acc[mt][nt][3] + bvy) * scy;
                if (SPLITOUT) {
                    __nv_bfloat16* Chi = Chi_all + (size_t)b * M * N;
                    __nv_bfloat16* Clo = Clo_all + (size_t)b * M * N;
                    __nv_bfloat162 h0 = __floats2bfloat162_rn(v0x, v0y);
                    __nv_bfloat162 l0 = __floats2bfloat162_rn(v0x - __bfloat162float(h0.x),
                                                              v0y - __bfloat162float(h0.y));
                    __nv_bfloat162 h1 = __floats2bfloat162_rn(v1x, v1y);
                    __nv_bfloat162 l1 = __floats2bfloat162_rn(v1x - __bfloat162float(h1.x),
                                                              v1y - __bfloat162float(h1.y));
                    *(__nv_bfloat162*)&Chi[(size_t)r0 * N + cx] = h0;
                    *(__nv_bfloat162*)&Clo[(size_t)r0 * N + cx] = l0;
                    *(__nv_bfloat162*)&Chi[(size_t)r1 * N + cx] = h1;
                    *(__nv_bfloat162*)&Clo[(size_t)r1 * N + cx] = l1;
                } else {
                    float* C = C_all + (size_t)b * M * N;
                    *(float2*)&C[(size_t)r0 * N + cx] = make_float2(v0x, v0y);
                    *(float2*)&C[(size_t)r1 * N + cx] = make_float2(v1x, v1y);
                }
            }
        } else {
            float* C = C_all + (size_t)b * M * N;
            const float bv0 = bias[r0], bv1 = bias[r1];
            const float sc0 = (r0 < scale_limit) ? scale : 1.0f;
            const float sc1 = (r1 < scale_limit) ? scale : 1.0f;
            #pragma unroll
            for (int nt = 0; nt < 4; nt++) {
                float2 v0, v1;
                v0.x = (acc[mt][nt][0] + bv0) * sc0;
                v0.y = (acc[mt][nt][1] + bv0) * sc0;
                v1.x = (acc[mt][nt][2] + bv1) * sc1;
                v1.y = (acc[mt][nt][3] + bv1) * sc1;
                *(float2*)&C[(size_t)r0 * N + col0 + nt * 8] = v0;
                *(float2*)&C[(size_t)r1 * N + col0 + nt * 8] = v1;
            }
        }
    }
}

// ---------------- HMMA fused attention v3: register Q, head-split warps -----
// Warp (wq, w2) owns q-band wq*16 and heads w2*4..w2*4+3 over the FULL 32-k
// tile. Q fragments for its 4 heads are hoisted to registers once. The only
// cross-warp data is the per-(q,k) partial head-sum (scalar), exchanged via a
// [pos][lane] smem buffer. W fragments are built in registers (C->A fragment
// identity) and consumed immediately. K/V double-buffered via cp.async; Q's
// smem region is reused as buffer 1 after fragment hoisting. 2 syncs/iter.
#define AT_BUF(i)  ((i) * 67584)
#define AT_KHI(i)  (AT_BUF(i) + 0)
#define AT_KLO(i)  (AT_BUF(i) + 16896)
#define AT_VHI(i)  (AT_BUF(i) + 33792)
#define AT_VLO(i)  (AT_BUF(i) + 50688)
#define AT_QHI     67584
#define AT_QLO     101376
#define AT_EXCH    135168          // [wq(4)][w2(2)][pos(16)][lane(32)] f32 = 16 KB
#define AT_TOTAL   151552

__global__ __launch_bounds__(256, 1) void attn_mma_kernel(
    const __nv_bfloat16* __restrict__ qt_hi, const __nv_bfloat16* __restrict__ qt_lo,
    float* __restrict__ attn_out)
{
    extern __shared__ char sm[];
    const uint32_t sb = smem_u32(sm);
    const int tid = threadIdx.x, lane = tid & 31, wid = tid >> 5;
    const int wq = wid >> 1, w2 = wid & 1;
    const int qr0 = wq * 16;
    const int b = blockIdx.y, qbase = blockIdx.x * 64;
    const __nv_bfloat16* qth = qt_hi + (size_t)b * HW * DQKV;
    const __nv_bfloat16* qtl = qt_lo + (size_t)b * HW * DQKV;

    const int ar  = (lane & 7) + ((lane >> 3) & 1) * 8;  // A rows / trans-B k-rows
    const int ak  = ((lane >> 3) >> 1) * 8;
    const int br_ = (lane & 7);
    const int bk  = ((lane >> 3) & 1) * 8;

    // ---- prologue: Q, K0, V0 in one group ----
    for (int i = tid; i < 2048; i += 256) {
        const int r = i >> 5, c = i & 31;
        const size_t so = (size_t)(qbase + r) * DQKV + c * 8;
        CP_ASYNC16(sb + AT_QHI + r * 528 + c * 16, qth + so);
        CP_ASYNC16(sb + AT_QLO + r * 528 + c * 16, qtl + so);
    }
    for (int i = tid; i < 1024; i += 256) {
        const int r = i >> 5, c = i & 31;
        const size_t sk = (size_t)r * DQKV + 256 + c * 8;
        const size_t sv = (size_t)r * DQKV + 512 + c * 8;
        CP_ASYNC16(sb + AT_KHI(0) + r * 528 + c * 16, qth + sk);
        CP_ASYNC16(sb + AT_KLO(0) + r * 528 + c * 16, qtl + sk);
        CP_ASYNC16(sb + AT_VHI(0) + r * 528 + c * 16, qth + sv);
        CP_ASYNC16(sb + AT_VLO(0) + r * 528 + c * 16, qtl + sv);
    }
    CP_COMMIT();
    CP_WAIT0();
    __syncthreads();

    // ---- hoist Q fragments for this warp's 4 heads (once) ----
    uint32_t qfh[4][2][4], qfl[4][2][4];
    #pragma unroll
    for (int h4 = 0; h4 < 4; h4++) {
        const int habs = w2 * 4 + h4;
        #pragma unroll
        for (int ks = 0; ks < 2; ks++) {
            const int dco = habs * 32 + ks * 16;
            const uint32_t aoff = (uint32_t)((qr0 + ar) * 528 + (dco + ak) * 2);
            LDSM_X4(qfh[h4][ks][0], qfh[h4][ks][1], qfh[h4][ks][2], qfh[h4][ks][3],
                    sb + AT_QHI + aoff);
            LDSM_X4(qfl[h4][ks][0], qfl[h4][ks][1], qfl[h4][ks][2], qfl[h4][ks][3],
                    sb + AT_QLO + aoff);
        }
    }
    __syncthreads();   // Q region free -> becomes K/V buffer 1

    float acc[4][4][4] = {};   // [h4][d-subtile][c]

    for (int it = 0; it < 32; it++) {
        const int buf = it & 1;
        // prefetch next K+V into the other buffer (overlaps whole iteration)
        if (it < 31) {
            const int kt = (it + 1) * 32;
            const uint32_t db = sb + AT_BUF(buf ^ 1);
            for (int i = tid; i < 1024; i += 256) {
                const int r = i >> 5, c = i & 31;
                const size_t sk = (size_t)(kt + r) * DQKV + 256 + c * 8;
                const size_t sv = (size_t)(kt + r) * DQKV + 512 + c * 8;
                CP_ASYNC16(db + 0     + r * 528 + c * 16, qth + sk);
                CP_ASYNC16(db + 16896 + r * 528 + c * 16, qtl + sk);
                CP_ASYNC16(db + 33792 + r * 528 + c * 16, qth + sv);
                CP_ASYNC16(db + 50688 + r * 528 + c * 16, qtl + sv);
            }
            CP_COMMIT();
        }

        // ---- logits: own 4 heads x 16q x 32k ----
        float lg[4][4][4] = {};
        const uint32_t khib = sb + AT_KHI(buf), klob = sb + AT_KLO(buf);
        #pragma unroll
        for (int h4 = 0; h4 < 4; h4++) {
            const int habs = w2 * 4 + h4;
            #pragma unroll
            for (int ks = 0; ks < 2; ks++) {
                const int dco = habs * 32 + ks * 16;
                #pragma unroll
                for (int nt = 0; nt < 4; nt++) {
                    uint32_t bH[2], bL[2];
                    const uint32_t boff = (uint32_t)((nt * 8 + br_) * 528 +
                                                     (dco + bk) * 2);
                    LDSM_X2(bH[0], bH[1], khib + boff);
                    LDSM_X2(bL[0], bL[1], klob + boff);
                    mma_bf16(lg[h4][nt], qfh[h4][ks], bH);
                    mma_bf16(lg[h4][nt], qfh[h4][ks], bL);
                    mma_bf16(lg[h4][nt], qfl[h4][ks], bH);
                }
            }
        }

        // ---- exp in place + partial head-sums -> exchange buffer ----
        #pragma unroll
        for (int nt = 0; nt < 4; nt++) {
            #pragma unroll
            for (int c = 0; c < 4; c++) {
                float s = 0.0f;
                #pragma unroll
                for (int h4 = 0; h4 < 4; h4++) {
                    lg[h4][nt][c] = fast_exp(lg[h4][nt][c]);
                    s += lg[h4][nt][c];
                }
                const uint32_t eo = AT_EXCH +
                    (uint32_t)((((wq * 2 + w2) * 16) + nt * 4 + c) * 128 + lane * 4);
                *(float*)(sm + eo) = s;
            }
        }
        __syncthreads();   // partials visible (and K consumed by all warps)

        // read both partials, form 1/sum
        float inv[4][4];
        #pragma unroll
        for (int nt = 0; nt < 4; nt++) {
            #pragma unroll
            for (int c = 0; c < 4; c++) {
                const uint32_t base = AT_EXCH +
                    (uint32_t)(((wq * 2) * 16 + nt * 4 + c) * 128 + lane * 4);
                const float s0 = *(float*)(sm + base);
                const float s1 = *(float*)(sm + base + 16 * 128);
                inv[nt][c] = 1.0f / (s0 + s1);
            }
        }

        // ---- AV: W fragments built in registers, V via ldmatrix.trans ----
        const uint32_t vhib = sb + AT_VHI(buf), vlob = sb + AT_VLO(buf);
        #pragma unroll
        for (int h4 = 0; h4 < 4; h4++) {
            const int habs = w2 * 4 + h4;
            #pragma unroll
            for (int ks = 0; ks < 2; ks++) {
                // A-fragment (16q x 16k) from C-fragments of nt=2ks, 2ks+1
                uint32_t wh[4], wl[4];
                {
                    const int n0t = 2 * ks, n1t = 2 * ks + 1;
                    const float a0 = lg[h4][n0t][0] * inv[n0t][0];
                    const float a1 = lg[h4][n0t][1] * inv[n0t][1];
                    const float a2 = lg[h4][n0t][2] * inv[n0t][2];
                    const float a3 = lg[h4][n0t][3] * inv[n0t][3];
                    const float b0 = lg[h4][n1t][0] * inv[n1t][0];
                    const float b1 = lg[h4][n1t][1] * inv[n1t][1];
                    const float b2 = lg[h4][n1t][2] * inv[n1t][2];
                    const float b3 = lg[h4][n1t][3] * inv[n1t][3];
                    __nv_bfloat162 h01 = __floats2bfloat162_rn(a0, a1);
                    __nv_bfloat162 h23 = __floats2bfloat162_rn(a2, a3);
                    __nv_bfloat162 g01 = __floats2bfloat162_rn(b0, b1);
                    __nv_bfloat162 g23 = __floats2bfloat162_rn(b2, b3);
                    __nv_bfloat162 l01 = __floats2bfloat162_rn(a0 - __bfloat162float(h01.x),
                                                               a1 - __bfloat162float(h01.y));
                    __nv_bfloat162 l23 = __floats2bfloat162_rn(a2 - __bfloat162float(h23.x),
                                                               a3 - __bfloat162float(h23.y));
                    __nv_bfloat162 m01 = __floats2bfloat162_rn(b0 - __bfloat162float(g01.x),
                                                               b1 - __bfloat162float(g01.y));
                    __nv_bfloat162 m23 = __floats2bfloat162_rn(b2 - __bfloat162float(g23.x),
                                                               b3 - __bfloat162float(g23.y));
                    wh[0] = *(uint32_t*)&h01; wh[1] = *(uint32_t*)&h23;
                    wh[2] = *(uint32_t*)&g01; wh[3] = *(uint32_t*)&g23;
                    wl[0] = *(uint32_t*)&l01; wl[1] = *(uint32_t*)&l23;
                    wl[2] = *(uint32_t*)&m01; wl[3] = *(uint32_t*)&m23;
                }
                #pragma unroll
                for (int nt = 0; nt < 4; nt++) {
                    uint32_t vH[2], vL[2];
                    const uint32_t boff = (uint32_t)((ks * 16 + ar) * 528 +
                                                     (habs * 32 + nt * 8) * 2);
                    LDSM_X2T(vH[0], vH[1], vhib + boff);
                    LDSM_X2T(vL[0], vL[1], vlob + boff);
                    mma_bf16(acc[h4][nt], wh, vH);
                    mma_bf16(acc[h4][nt], wh, vL);
                    mma_bf16(acc[h4][nt], wl, vH);
                }
            }
        }

        if (it < 31) {
            CP_WAIT0();       // next K+V arrived
            __syncthreads();  // visible to all; current buffers fully consumed
        }
    }

    // ---- epilogue: reference-reshape layout ----
    float* ab = attn_out + (size_t)b * DVDIM * HW;
    #pragma unroll
    for (int h4 = 0; h4 < 4; h4++) {
        const int habs = w2 * 4 + h4;
        #pragma unroll
        for (int nt = 0; nt < 4; nt++) {
            const int q0g = qbase + qr0 + (lane >> 2);
            const int q1g = q0g + 8;
            const int d   = nt * 8 + (lane & 3) * 2;
            const int ch0 = habs * 32 + (q0g >> 5), sp0 = (q0g & 31) * 32 + d;
            const int ch1 = habs * 32 + (q1g >> 5), sp1 = (q1g & 31) * 32 + d;
            *(float2*)&ab[(size_t)ch0 * HW + sp0] = make_float2(acc[h4][nt][0], acc[h4][nt][1]);
            *(float2*)&ab[(size_t)ch1 * HW + sp1] = make_float2(acc[h4][nt][2], acc[h4][nt][3]);
        }
    }
}

// ---------------------------------------------------------------------------
extern "C" void kernel_launch(void* const* d_in, const int* in_sizes, int n_in,
                              void* d_out, int out_size)
{
    const float* x      = (const float*)d_in[0];
    const float* w_qkv  = (const float*)d_in[1];
    const float* b_qkv  = (const float*)d_in[2];
    const float* w_attn = (const float*)d_in[3];
    const float* b_attn = (const float*)d_in[4];
    float* out = (float*)d_out;

    float* attn; cudaGetSymbolAddress((void**)&attn, g_attn);
    __nv_bfloat16 *qth, *qtl, *wqh, *wql, *wah, *wal, *xth, *xtl, *ath, *atl;
    cudaGetSymbolAddress((void**)&qth, g_qt_hi);
    cudaGetSymbolAddress((void**)&qtl, g_qt_lo);
    cudaGetSymbolAddress((void**)&wqh, g_wqkv_hi);
    cudaGetSymbolAddress((void**)&wql, g_wqkv_lo);
    cudaGetSymbolAddress((void**)&wah, g_wattn_hi);
    cudaGetSymbolAddress((void**)&wal, g_wattn_lo);
    cudaGetSymbolAddress((void**)&xth, g_xt_hi);
    cudaGetSymbolAddress((void**)&xtl, g_xt_lo);
    cudaGetSymbolAddress((void**)&ath, g_at_hi);
    cudaGetSymbolAddress((void**)&atl, g_at_lo);

    cudaFuncSetAttribute(gemm_mma<CIN, true, true>,
                         cudaFuncAttributeMaxDynamicSharedMemorySize, GM_SMEM);
    cudaFuncSetAttribute(gemm_mma<DVDIM, false, false>,
                         cudaFuncAttributeMaxDynamicSharedMemorySize, GM_SMEM);
    cudaFuncSetAttribute(attn_mma_kernel,
                         cudaFuncAttributeMaxDynamicSharedMemorySize, AT_TOTAL);

    // 0) precision-split weights; transpose+split x
    split_kernel<<<(DQKV * CIN + 255) / 256, 256>>>(w_qkv, wqh, wql, DQKV * CIN);
    split_kernel<<<(COUT * DVDIM + 255) / 256, 256>>>(w_attn, wah, wal, COUT * DVDIM);
    {
        dim3 grid(HW / 32, CIN / 32, BATCH);
        tsplit_kernel<<<grid, dim3(32, 8)>>>(x, xth, xtl, CIN, HW);
    }

    // 1) QKV projection TRANSPOSED, bf16 hi/lo output (+colbias, Q cols scaled)
    {
        dim3 grid(DQKV / 128, HW / 128, BATCH); // (6, 8, 8)
        gemm_mma<CIN, true, true><<<grid, 256, GM_SMEM>>>(
            xth, xtl, wqh, wql, b_qkv, nullptr, qth, qtl,
            HW, DQKV, (size_t)HW * CIN, 0, 256, 0.17677669529663687f);
    }

    // 2) fused HMMA attention v3 (head-axis softmax) -> g_attn
    {
        dim3 grid(HW / 64, BATCH); // (16, 8)
        attn_mma_kernel<<<grid, 256, AT_TOTAL>>>(qth, qtl, attn);
    }

    // 2.5) transpose+split attention output for GEMM3's B operand
    {
        dim3 grid(HW / 32, DVDIM / 32, BATCH);
        tsplit_kernel<<<grid, dim3(32, 8)>>>(attn, ath, atl, DVDIM, HW);
    }

    // 3) output projection (+row bias, fp32 out)
    {
        dim3 grid(HW / 128, COUT / 128, BATCH); // (8, 4, 8)
        gemm_mma<DVDIM, false, false><<<grid, 256, GM_SMEM>>>(
            wah, wal, ath, atl, b_attn, out, nullptr, nullptr,
            COUT, HW, 0, (size_t)HW * DVDIM, 0, 1.0f);
    }
}